// round 13
// baseline (speedup 1.0000x reference)
#include <cuda_runtime.h>
#include <math.h>

#define HH 512
#define WW 512
#define NB 64
#define PD 15
#define RB 32                 // rows per band (per CTA)
#define BANDS (HH / RB)       // 16
#define GG 4                  // rows per smem group
#define NGROUPS (RB / GG)     // 8
#define NTH 256
#define SBW 560               // swizzled row width
#define NBLOCKS (BANDS * NB)  // 1024

__device__ __forceinline__ int scol(int c) { return c + (c >> 5); }

// sigmoid(x) = 0.5 * (1 + tanh(x/2)) using HW tanh.approx (sm_75+)
__device__ __forceinline__ float fast_sigmoid(float x) {
    float th;
    asm("tanh.approx.f32 %0, %1;" : "=f"(th) : "f"(0.5f * x));
    return fmaf(0.5f, th, 0.5f);
}

__device__ float g_part[NB * BANDS * 2];
__device__ unsigned int g_count = 0;

__global__ __launch_bounds__(NTH, 7)
void fused_kernel(const float* __restrict__ pred, const float* __restrict__ mask,
                  float* __restrict__ out) {
    __shared__ float buf[2][GG][SBW];
    __shared__ float s_i[8], s_u[8];
    __shared__ bool amLast;

    const int t    = threadIdx.x;           // owns column pair (2t, 2t+1) in phase A
    const int band = blockIdx.x;
    const int b    = blockIdx.y;
    const int r0   = band * RB;
    const float*  mb  = mask + (size_t)b * HH * WW;
    const float*  pb  = pred + (size_t)b * HH * WW;
    const float2* mb2 = reinterpret_cast<const float2*>(mb);
    const int ca = 2 * t;                   // phase-A base column

    // zero both buffers once (halo regions stay zero thereafter)
    #pragma unroll
    for (int i = t; i < 2 * GG * SBW; i += NTH) ((float*)buf)[i] = 0.f;

    // vertical running-sum init: 30 rows [r0-15, r0+14], float2, 4-way ILP tree
    float s0, s1;
    {
        float2 a0 = {0.f, 0.f}, a1 = {0.f, 0.f}, a2 = {0.f, 0.f}, a3 = {0.f, 0.f};
        #pragma unroll
        for (int j = 0; j < 28; j += 4) {
            int g0 = r0 - PD + j;
            if (g0 + 0 >= 0) { float2 v = mb2[(g0 + 0) * (WW/2) + t]; a0.x += v.x; a0.y += v.y; }
            if (g0 + 1 >= 0) { float2 v = mb2[(g0 + 1) * (WW/2) + t]; a1.x += v.x; a1.y += v.y; }
            if (g0 + 2 >= 0) { float2 v = mb2[(g0 + 2) * (WW/2) + t]; a2.x += v.x; a2.y += v.y; }
            if (g0 + 3 >= 0) { float2 v = mb2[(g0 + 3) * (WW/2) + t]; a3.x += v.x; a3.y += v.y; }
        }
        int g28 = r0 - PD + 28, g29 = r0 - PD + 29;
        if (g28 >= 0) { float2 v = mb2[g28 * (WW/2) + t]; a0.x += v.x; a0.y += v.y; }
        if (g29 >= 0) { float2 v = mb2[g29 * (WW/2) + t]; a1.x += v.x; a1.y += v.y; }
        s0 = (a0.x + a1.x) + (a2.x + a3.x);
        s1 = (a0.y + a1.y) + (a2.y + a3.y);
    }

    // zeroing must complete before any staged interior write
    __syncthreads();

    // ---- prologue: phase A for group 0 into buf[0] ----
    #pragma unroll
    for (int rr = 0; rr < GG; ++rr) {
        int gr = r0 + rr;
        float2 lead = (gr + PD < HH) ? mb2[(gr + PD) * (WW/2) + t] : make_float2(0.f, 0.f);
        s0 += lead.x; s1 += lead.y;
        buf[0][rr][scol(ca + PD)]     = s0;
        buf[0][rr][scol(ca + PD + 1)] = s1;
        float2 trail = (gr - PD >= 0) ? mb2[(gr - PD) * (WW/2) + t] : make_float2(0.f, 0.f);
        s0 -= trail.x; s1 -= trail.y;
    }
    __syncthreads();

    const float inv = 1.0f / 961.0f;
    float fi = 0.f, fu = 0.f;

    // phase-B mapping: 64 threads per row, 8 cols per thread
    const int rg   = t >> 6;                // 0..3 row-in-group
    const int c0   = (t & 63) * 8;          // 8-chunk base (buffer idx)
    const int lane = t & 31;

    for (int g = 0; g < NGROUPS; ++g) {
        // ---- phase A for group g+1 into buf[(g+1)&1] (overlaps phase B) ----
        if (g + 1 < NGROUPS) {
            const int rbase = r0 + (g + 1) * GG;
            float* bw = &buf[(g + 1) & 1][0][0];
            #pragma unroll
            for (int rr = 0; rr < GG; ++rr) {
                int gr = rbase + rr;
                float2 lead = (gr + PD < HH) ? mb2[(gr + PD) * (WW/2) + t] : make_float2(0.f, 0.f);
                s0 += lead.x; s1 += lead.y;
                bw[rr * SBW + scol(ca + PD)]     = s0;
                bw[rr * SBW + scol(ca + PD + 1)] = s1;
                float2 trail = (gr - PD >= 0) ? mb2[(gr - PD) * (WW/2) + t] : make_float2(0.f, 0.f);
                s0 -= trail.x; s1 -= trail.y;
            }
        }

        // ---- phase B for group g from buf[g&1] ----
        {
            const int grB = r0 + g * GG + rg;
            const float* br = &buf[g & 1][rg][0];
            const float* mrow = mb + grB * WW + c0;
            const float* prow = pb + grB * WW + c0;

            // own chunk: buffer idx [c0, c0+7] (also the slide-subtract values)
            float o0 = br[scol(c0 + 0)], o1 = br[scol(c0 + 1)];
            float o2 = br[scol(c0 + 2)], o3 = br[scol(c0 + 3)];
            float o4 = br[scol(c0 + 4)], o5 = br[scol(c0 + 5)];
            float o6 = br[scol(c0 + 6)], o7 = br[scol(c0 + 7)];
            float S = ((o0 + o1) + (o2 + o3)) + ((o4 + o5) + (o6 + o7));
            float U = S - o7;

            // window init = idx [c0, c0+30] = S_l + S_{l+1} + S_{l+2} + U_{l+3}
            float s1f = __shfl_down_sync(0xffffffffu, S, 1);
            float s2f = __shfl_down_sync(0xffffffffu, S, 2);
            float u3f = __shfl_down_sync(0xffffffffu, U, 3);
            float hs = S + s1f + s2f + u3f;

            // lanes 29..31: neighbor chunks cross the warp edge -> direct LDS
            if (lane >= 29) {
                float a0 = 0.f, a1 = 0.f, a2 = 0.f, a3 = 0.f;
                #pragma unroll
                for (int j = 8; j < 28; j += 4) {
                    a0 += br[scol(c0 + j + 0)];
                    a1 += br[scol(c0 + j + 1)];
                    a2 += br[scol(c0 + j + 2)];
                    a3 += br[scol(c0 + j + 3)];
                }
                a0 += br[scol(c0 + 28)];
                a1 += br[scol(c0 + 29)];
                a2 += br[scol(c0 + 30)];
                hs = S + (a0 + a1) + (a2 + a3);
            }

            float own[8] = {o0, o1, o2, o3, o4, o5, o6, o7};

            // two 4-column register batches; subtract side from cached regs
            #pragma unroll
            for (int h = 0; h < 2; ++h) {
                float4 m4 = *reinterpret_cast<const float4*>(mrow + h * 4);
                float4 p4 = *reinterpret_cast<const float4*>(prow + h * 4);
                float mk[4] = {m4.x, m4.y, m4.z, m4.w};
                float pr[4] = {p4.x, p4.y, p4.z, p4.w};
                #pragma unroll
                for (int q = 0; q < 4; ++q) {
                    int c = c0 + h * 4 + q;
                    float avg  = hs * inv;
                    float weit = fmaf(5.f, fabsf(avg - mk[q]), 1.f);
                    float p    = fast_sigmoid(pr[q]);
                    fi = fmaf(p * mk[q], weit, fi);
                    fu = fmaf(p + mk[q], weit, fu);
                    hs += br[scol(c + 31)] - own[h * 4 + q];
                }
            }
        }
        __syncthreads();
    }

    // ---- block reduce 256 -> 1 ----
    #pragma unroll
    for (int o = 16; o; o >>= 1) {
        fi += __shfl_down_sync(0xffffffffu, fi, o);
        fu += __shfl_down_sync(0xffffffffu, fu, o);
    }
    int wid = t >> 5;
    if (lane == 0) { s_i[wid] = fi; s_u[wid] = fu; }
    __syncthreads();
    if (wid == 0) {
        float ti = (lane < 8) ? s_i[lane] : 0.f;
        float tu = (lane < 8) ? s_u[lane] : 0.f;
        #pragma unroll
        for (int o = 4; o; o >>= 1) {
            ti += __shfl_down_sync(0xffffffffu, ti, o);
            tu += __shfl_down_sync(0xffffffffu, tu, o);
        }
        if (lane == 0) {
            g_part[(b * BANDS + band) * 2 + 0] = ti;
            g_part[(b * BANDS + band) * 2 + 1] = tu;
            __threadfence();
            unsigned int done = atomicAdd(&g_count, 1u);
            amLast = (done == NBLOCKS - 1);
        }
    }
    __syncthreads();

    // ---- last CTA: finalize ----
    if (amLast) {
        double w = 0.0;
        if (t < NB) {
            double it = 0.0, un = 0.0;
            #pragma unroll
            for (int p = 0; p < BANDS; ++p) {
                it += (double)g_part[(t * BANDS + p) * 2 + 0];
                un += (double)g_part[(t * BANDS + p) * 2 + 1];
            }
            w = 1.0 - (2.0 * it + 0.5) / (un + 0.5);
        }
        #pragma unroll
        for (int o = 16; o; o >>= 1) w += __shfl_down_sync(0xffffffffu, w, o);
        __shared__ double sh[2];
        if (t < 64 && (t & 31) == 0) sh[t >> 5] = w;
        __syncthreads();
        if (t == 0) {
            out[0] = (float)((sh[0] + sh[1]) / (double)NB);
            g_count = 0;   // reset for next graph replay
        }
    }
}

extern "C" void kernel_launch(void* const* d_in, const int* in_sizes, int n_in,
                              void* d_out, int out_size) {
    const float* pred = (const float*)d_in[0];
    const float* mask = (const float*)d_in[1];
    float* out = (float*)d_out;

    fused_kernel<<<dim3(BANDS, NB), NTH>>>(pred, mask, out);
}

// round 14
// speedup vs baseline: 1.1428x; 1.1428x over previous
#include <cuda_runtime.h>
#include <math.h>

#define HH 512
#define WW 512
#define NB 64
#define PD 15
#define RB 32                 // rows per band (per CTA)
#define BANDS (HH / RB)       // 16
#define GG 4                  // rows per smem group
#define NGROUPS (RB / GG)     // 8
#define NTH 256
#define SBW 560               // swizzled row width
#define NBLOCKS (BANDS * NB)  // 1024

__device__ __forceinline__ int scol(int c) { return c + (c >> 5); }

// sigmoid(x) = 0.5 * (1 + tanh(x/2)) using HW tanh.approx (sm_75+)
__device__ __forceinline__ float fast_sigmoid(float x) {
    float th;
    asm("tanh.approx.f32 %0, %1;" : "=f"(th) : "f"(0.5f * x));
    return fmaf(0.5f, th, 0.5f);
}

__device__ float g_part[NB * BANDS * 2];
__device__ unsigned int g_count = 0;

__global__ __launch_bounds__(NTH, 6)
void fused_kernel(const float* __restrict__ pred, const float* __restrict__ mask,
                  float* __restrict__ out) {
    __shared__ float buf[2][GG][SBW];
    __shared__ float s_i[8], s_u[8];
    __shared__ bool amLast;

    const int t    = threadIdx.x;           // owns column pair (2t, 2t+1) in phase A
    const int band = blockIdx.x;
    const int b    = blockIdx.y;
    const int r0   = band * RB;
    const float*  mb  = mask + (size_t)b * HH * WW;
    const float*  pb  = pred + (size_t)b * HH * WW;
    const float2* mb2 = reinterpret_cast<const float2*>(mb);
    const int ca = 2 * t;                   // phase-A base column

    // zero both buffers once (halo regions stay zero thereafter)
    #pragma unroll
    for (int i = t; i < 2 * GG * SBW; i += NTH) ((float*)buf)[i] = 0.f;

    // vertical running-sum init: 30 rows [r0-15, r0+14], float2, 4-way ILP tree
    float s0, s1;
    {
        float2 a0 = {0.f, 0.f}, a1 = {0.f, 0.f}, a2 = {0.f, 0.f}, a3 = {0.f, 0.f};
        #pragma unroll
        for (int j = 0; j < 28; j += 4) {
            int g0 = r0 - PD + j;
            if (g0 + 0 >= 0) { float2 v = mb2[(g0 + 0) * (WW/2) + t]; a0.x += v.x; a0.y += v.y; }
            if (g0 + 1 >= 0) { float2 v = mb2[(g0 + 1) * (WW/2) + t]; a1.x += v.x; a1.y += v.y; }
            if (g0 + 2 >= 0) { float2 v = mb2[(g0 + 2) * (WW/2) + t]; a2.x += v.x; a2.y += v.y; }
            if (g0 + 3 >= 0) { float2 v = mb2[(g0 + 3) * (WW/2) + t]; a3.x += v.x; a3.y += v.y; }
        }
        int g28 = r0 - PD + 28, g29 = r0 - PD + 29;
        if (g28 >= 0) { float2 v = mb2[g28 * (WW/2) + t]; a0.x += v.x; a0.y += v.y; }
        if (g29 >= 0) { float2 v = mb2[g29 * (WW/2) + t]; a1.x += v.x; a1.y += v.y; }
        s0 = (a0.x + a1.x) + (a2.x + a3.x);
        s1 = (a0.y + a1.y) + (a2.y + a3.y);
    }

    // zeroing must complete before any staged interior write
    __syncthreads();

    // ---- prologue: phase A for group 0 into buf[0] ----
    #pragma unroll
    for (int rr = 0; rr < GG; ++rr) {
        int gr = r0 + rr;
        float2 lead = (gr + PD < HH) ? mb2[(gr + PD) * (WW/2) + t] : make_float2(0.f, 0.f);
        s0 += lead.x; s1 += lead.y;
        buf[0][rr][scol(ca + PD)]     = s0;
        buf[0][rr][scol(ca + PD + 1)] = s1;
        float2 trail = (gr - PD >= 0) ? mb2[(gr - PD) * (WW/2) + t] : make_float2(0.f, 0.f);
        s0 -= trail.x; s1 -= trail.y;
    }
    __syncthreads();

    const float inv = 1.0f / 961.0f;
    float fi = 0.f, fu = 0.f;

    // phase-B mapping: 64 threads per row, 8 cols per thread
    const int rg   = t >> 6;                // 0..3 row-in-group
    const int c0   = (t & 63) * 8;          // 8-chunk base (buffer idx)
    const int lane = t & 31;

    for (int g = 0; g < NGROUPS; ++g) {
        // ---- phase A for group g+1 into buf[(g+1)&1] (overlaps phase B) ----
        if (g + 1 < NGROUPS) {
            const int rbase = r0 + (g + 1) * GG;
            float* bw = &buf[(g + 1) & 1][0][0];
            #pragma unroll
            for (int rr = 0; rr < GG; ++rr) {
                int gr = rbase + rr;
                float2 lead = (gr + PD < HH) ? mb2[(gr + PD) * (WW/2) + t] : make_float2(0.f, 0.f);
                s0 += lead.x; s1 += lead.y;
                bw[rr * SBW + scol(ca + PD)]     = s0;
                bw[rr * SBW + scol(ca + PD + 1)] = s1;
                float2 trail = (gr - PD >= 0) ? mb2[(gr - PD) * (WW/2) + t] : make_float2(0.f, 0.f);
                s0 -= trail.x; s1 -= trail.y;
            }
        }

        // ---- phase B for group g from buf[g&1] ----
        {
            const int grB = r0 + g * GG + rg;
            const float* br = &buf[g & 1][rg][0];
            const float* mrow = mb + grB * WW + c0;
            const float* prow = pb + grB * WW + c0;

            // own chunk: buffer idx [c0, c0+7] (also the slide-subtract values)
            float o0 = br[scol(c0 + 0)], o1 = br[scol(c0 + 1)];
            float o2 = br[scol(c0 + 2)], o3 = br[scol(c0 + 3)];
            float o4 = br[scol(c0 + 4)], o5 = br[scol(c0 + 5)];
            float o6 = br[scol(c0 + 6)], o7 = br[scol(c0 + 7)];
            float S = ((o0 + o1) + (o2 + o3)) + ((o4 + o5) + (o6 + o7));
            float U = S - o7;

            // window init = idx [c0, c0+30] = S_l + S_{l+1} + S_{l+2} + U_{l+3}
            float s1f = __shfl_down_sync(0xffffffffu, S, 1);
            float s2f = __shfl_down_sync(0xffffffffu, S, 2);
            float u3f = __shfl_down_sync(0xffffffffu, U, 3);
            float hs = S + s1f + s2f + u3f;

            // lanes 29..31: neighbor chunks cross the warp edge -> direct LDS
            if (lane >= 29) {
                float a0 = 0.f, a1 = 0.f, a2 = 0.f, a3 = 0.f;
                #pragma unroll
                for (int j = 8; j < 28; j += 4) {
                    a0 += br[scol(c0 + j + 0)];
                    a1 += br[scol(c0 + j + 1)];
                    a2 += br[scol(c0 + j + 2)];
                    a3 += br[scol(c0 + j + 3)];
                }
                a0 += br[scol(c0 + 28)];
                a1 += br[scol(c0 + 29)];
                a2 += br[scol(c0 + 30)];
                hs = S + (a0 + a1) + (a2 + a3);
            }

            float own[8] = {o0, o1, o2, o3, o4, o5, o6, o7};

            // two 4-column register batches; subtract side from cached regs
            #pragma unroll
            for (int h = 0; h < 2; ++h) {
                float4 m4 = *reinterpret_cast<const float4*>(mrow + h * 4);
                float4 p4 = *reinterpret_cast<const float4*>(prow + h * 4);
                float mk[4] = {m4.x, m4.y, m4.z, m4.w};
                float pr[4] = {p4.x, p4.y, p4.z, p4.w};
                #pragma unroll
                for (int q = 0; q < 4; ++q) {
                    int c = c0 + h * 4 + q;
                    float avg  = hs * inv;
                    float weit = fmaf(5.f, fabsf(avg - mk[q]), 1.f);
                    float p    = fast_sigmoid(pr[q]);
                    fi = fmaf(p * mk[q], weit, fi);
                    fu = fmaf(p + mk[q], weit, fu);
                    hs += br[scol(c + 31)] - own[h * 4 + q];
                }
            }
        }
        __syncthreads();
    }

    // ---- block reduce 256 -> 1 ----
    #pragma unroll
    for (int o = 16; o; o >>= 1) {
        fi += __shfl_down_sync(0xffffffffu, fi, o);
        fu += __shfl_down_sync(0xffffffffu, fu, o);
    }
    int wid = t >> 5;
    if (lane == 0) { s_i[wid] = fi; s_u[wid] = fu; }
    __syncthreads();
    if (wid == 0) {
        float ti = (lane < 8) ? s_i[lane] : 0.f;
        float tu = (lane < 8) ? s_u[lane] : 0.f;
        #pragma unroll
        for (int o = 4; o; o >>= 1) {
            ti += __shfl_down_sync(0xffffffffu, ti, o);
            tu += __shfl_down_sync(0xffffffffu, tu, o);
        }
        if (lane == 0) {
            g_part[(b * BANDS + band) * 2 + 0] = ti;
            g_part[(b * BANDS + band) * 2 + 1] = tu;
            __threadfence();
            unsigned int done = atomicAdd(&g_count, 1u);
            amLast = (done == NBLOCKS - 1);
        }
    }
    __syncthreads();

    // ---- last CTA: finalize ----
    if (amLast) {
        double w = 0.0;
        if (t < NB) {
            double it = 0.0, un = 0.0;
            #pragma unroll
            for (int p = 0; p < BANDS; ++p) {
                it += (double)g_part[(t * BANDS + p) * 2 + 0];
                un += (double)g_part[(t * BANDS + p) * 2 + 1];
            }
            w = 1.0 - (2.0 * it + 0.5) / (un + 0.5);
        }
        #pragma unroll
        for (int o = 16; o; o >>= 1) w += __shfl_down_sync(0xffffffffu, w, o);
        __shared__ double sh[2];
        if (t < 64 && (t & 31) == 0) sh[t >> 5] = w;
        __syncthreads();
        if (t == 0) {
            out[0] = (float)((sh[0] + sh[1]) / (double)NB);
            g_count = 0;   // reset for next graph replay
        }
    }
}

extern "C" void kernel_launch(void* const* d_in, const int* in_sizes, int n_in,
                              void* d_out, int out_size) {
    const float* pred = (const float*)d_in[0];
    const float* mask = (const float*)d_in[1];
    float* out = (float*)d_out;

    fused_kernel<<<dim3(BANDS, NB), NTH>>>(pred, mask, out);
}